// round 13
// baseline (speedup 1.0000x reference)
#include <cuda_runtime.h>
#include <cstddef>

// GCNConv(16,8): out = D^-1/2 (A+I) D^-1/2 X W^T + b
// R7 structure at the measured LTS-RED-op floor, minus the redundant out-init:
//   hs[n]   = dinv[n] * (x[n] @ W^T),  dinv[n] = rsqrt(deg[n]+1)
//   out     = 0                           (async memset, overlapped)
//   out[d] += hs[s]      per edge         (k_scatter, 2x red.v4.f32)
//   out[n]  = (out[n] + hs[n])*dinv + b   (k_final, hs is L2-hot)

#define MAXN 500000

__device__ float g_hs[(size_t)MAXN * 8];    // 16 MB, L2-resident
__device__ float g_dinv[MAXN];
__device__ int   g_deg[MAXN];

// ---------------------------------------------------------------- degree count (4 edges/thread)
__global__ void k_deg(const int* __restrict__ dst, int E, int N) {
    int i = blockIdx.x * blockDim.x + threadIdx.x;
    int e = i * 4;
    if (e + 3 < E) {
        int4 d4 = __ldcs((const int4*)(dst + e));
        if ((unsigned)d4.x < (unsigned)N) atomicAdd(&g_deg[d4.x], 1);
        if ((unsigned)d4.y < (unsigned)N) atomicAdd(&g_deg[d4.y], 1);
        if ((unsigned)d4.z < (unsigned)N) atomicAdd(&g_deg[d4.z], 1);
        if ((unsigned)d4.w < (unsigned)N) atomicAdd(&g_deg[d4.w], 1);
    } else {
        for (; e < E; e++) {
            int d = dst[e];
            if ((unsigned)d < (unsigned)N) atomicAdd(&g_deg[d], 1);
        }
    }
}

// ---------------------------------------------------------------- node transform
// hs = dinv * (x @ W^T); hs only (out is zeroed by memset).
__global__ void k_node(const float* __restrict__ x, const float* __restrict__ W, int N) {
    __shared__ float sW[128];               // W is [8,16] row-major
    int t = threadIdx.x;
    if (t < 128) sW[t] = W[t];
    __syncthreads();

    int n = blockIdx.x * blockDim.x + t;
    if (n >= N) return;

    const float4* xp = (const float4*)(x + (size_t)n * 16);
    float4 v0 = __ldcs(xp), v1 = __ldcs(xp + 1), v2 = __ldcs(xp + 2), v3 = __ldcs(xp + 3);
    float xr[16] = { v0.x, v0.y, v0.z, v0.w,  v1.x, v1.y, v1.z, v1.w,
                     v2.x, v2.y, v2.z, v2.w,  v3.x, v3.y, v3.z, v3.w };

    float dinv = rsqrtf((float)(g_deg[n] + 1));   // +1 self loop; always > 0
    g_dinv[n] = dinv;

    float h[8];
#pragma unroll
    for (int j = 0; j < 8; j++) {
        float s = 0.f;
#pragma unroll
        for (int i = 0; i < 16; i++) s = fmaf(xr[i], sW[j * 16 + i], s);
        h[j] = s * dinv;
    }

    float4* hsp = (float4*)(g_hs + (size_t)n * 8);
    hsp[0] = make_float4(h[0], h[1], h[2], h[3]);
    hsp[1] = make_float4(h[4], h[5], h[6], h[7]);
}

// ---------------------------------------------------------------- edge scatter
// out[dst] += hs[src], 2 edges/thread, 2x red.v4.f32 per edge (op-count floor).
__global__ void k_scatter(const int* __restrict__ src,
                          const int* __restrict__ dst,
                          float* __restrict__ out, int E, int N) {
    int i = blockIdx.x * blockDim.x + threadIdx.x;
    int e = i * 2;
    if (e >= E) return;

    int2 s2, d2;
    if (e + 1 < E) {
        s2 = __ldcs((const int2*)(src + e));
        d2 = __ldcs((const int2*)(dst + e));
    } else {
        s2.x = src[e]; d2.x = dst[e];
        s2.y = 0;      d2.y = -1;           // fails bounds check
    }

#pragma unroll
    for (int j = 0; j < 2; j++) {
        int s = j ? s2.y : s2.x;
        int d = j ? d2.y : d2.x;
        if ((unsigned)s >= (unsigned)N || (unsigned)d >= (unsigned)N) continue;

        const float4* hp = (const float4*)(g_hs + (size_t)s * 8);
        float4 a = hp[0], c = hp[1];

        float* dp = out + (size_t)d * 8;
        asm volatile("red.global.add.v4.f32 [%0], {%1,%2,%3,%4};"
                     :: "l"(dp), "f"(a.x), "f"(a.y), "f"(a.z), "f"(a.w) : "memory");
        asm volatile("red.global.add.v4.f32 [%0], {%1,%2,%3,%4};"
                     :: "l"(dp + 4), "f"(c.x), "f"(c.y), "f"(c.z), "f"(c.w) : "memory");
    }
}

// ---------------------------------------------------------------- finalize
// out = (out + hs)*dinv + b   (hs supplies the self-loop term; L2-hot)
__global__ void k_final(const float* __restrict__ bias, float* __restrict__ out, int N) {
    int n = blockIdx.x * blockDim.x + threadIdx.x;
    if (n >= N) return;

    float dinv = g_dinv[n];
    const float4* bp = (const float4*)bias;
    float4 b0 = __ldg(bp), b1 = __ldg(bp + 1);

    const float4* hp = (const float4*)(g_hs + (size_t)n * 8);
    float4 h0 = hp[0], h1 = hp[1];

    float4* op = (float4*)(out + (size_t)n * 8);
    float4 a = op[0], c = op[1];
    a.x = fmaf(a.x + h0.x, dinv, b0.x); a.y = fmaf(a.y + h0.y, dinv, b0.y);
    a.z = fmaf(a.z + h0.z, dinv, b0.z); a.w = fmaf(a.w + h0.w, dinv, b0.w);
    c.x = fmaf(c.x + h1.x, dinv, b1.x); c.y = fmaf(c.y + h1.y, dinv, b1.y);
    c.z = fmaf(c.z + h1.z, dinv, b1.z); c.w = fmaf(c.w + h1.w, dinv, b1.w);
    op[0] = a; op[1] = c;
}

// ---------------------------------------------------------------- launch
extern "C" void kernel_launch(void* const* d_in, const int* in_sizes, int n_in,
                              void* d_out, int out_size) {
    const float* x    = (const float*)d_in[0];   // [N,16] f32
    const int*   ei   = (const int*)d_in[1];     // [2,E]  int32 (converted from int64)
    const float* W    = (const float*)d_in[2];   // [8,16] f32
    const float* bias = (const float*)d_in[3];   // [8]    f32
    float*       out  = (float*)d_out;           // [N,8]  f32

    int N = in_sizes[0] / 16;
    int E = in_sizes[1] / 2;
    const int* src = ei;
    const int* dst = ei + E;

    const int T = 256;
    int gbN  = (N + T - 1) / T;
    int gbE4 = (E / 4 + T - 1) / T + 1;      // 4 edges/thread (+1 tail block)
    int gbE2 = ((E + 1) / 2 + T - 1) / T;    // 2 edges/thread

    void* degp = nullptr;
    cudaGetSymbolAddress(&degp, g_deg);      // address query only, no allocation
    cudaMemsetAsync(degp, 0, (size_t)N * sizeof(int));
    cudaMemsetAsync(d_out, 0, (size_t)N * 8 * sizeof(float));   // accumulator base

    k_deg<<<gbE4, T>>>(dst, E, N);
    k_node<<<gbN, T>>>(x, W, N);
    k_scatter<<<gbE2, T>>>(src, dst, out, E, N);
    k_final<<<gbN, T>>>(bias, out, N);
}

// round 14
// speedup vs baseline: 1.4776x; 1.4776x over previous
#include <cuda_runtime.h>
#include <cstddef>

// GCNConv(16,8): out = D^-1/2 (A+I) D^-1/2 X W^T + b
// R7 structure (best measured: 114.8us). out-init in k_node doubles as the
// L2 pre-warm for the scatter REDs (R13 proved removing it costs ~50us).
//   hs[n]   = dinv[n] * (x[n] @ W^T),  dinv[n] = rsqrt(deg[n]+1)
//   out[n]  = hs[n]                       (init + L2 warm, k_node)
//   out[d] += hs[s]      per edge         (k_scatter, 1 edge/thread, 2x red.v4)
//   out[n]  = out[n]*dinv[n] + b          (k_final)

#define MAXN 500000

__device__ float g_hs[(size_t)MAXN * 8];    // 16 MB, L2-resident
__device__ float g_dinv[MAXN];
__device__ int   g_deg[MAXN];

// ---------------------------------------------------------------- degree count (4 edges/thread)
__global__ void k_deg(const int* __restrict__ dst, int E, int N) {
    int i = blockIdx.x * blockDim.x + threadIdx.x;
    int e = i * 4;
    if (e + 3 < E) {
        int4 d4 = *(const int4*)(dst + e);
        if ((unsigned)d4.x < (unsigned)N) atomicAdd(&g_deg[d4.x], 1);
        if ((unsigned)d4.y < (unsigned)N) atomicAdd(&g_deg[d4.y], 1);
        if ((unsigned)d4.z < (unsigned)N) atomicAdd(&g_deg[d4.z], 1);
        if ((unsigned)d4.w < (unsigned)N) atomicAdd(&g_deg[d4.w], 1);
    } else {
        for (; e < E; e++) {
            int d = dst[e];
            if ((unsigned)d < (unsigned)N) atomicAdd(&g_deg[d], 1);
        }
    }
}

// ---------------------------------------------------------------- node transform
// hs = dinv * (x @ W^T); out initialized to hs (self-loop msg + L2 warm).
__global__ void k_node(const float* __restrict__ x, const float* __restrict__ W,
                       float* __restrict__ out, int N) {
    __shared__ float sW[128];               // W is [8,16] row-major
    int t = threadIdx.x;
    if (t < 128) sW[t] = W[t];
    __syncthreads();

    int n = blockIdx.x * blockDim.x + t;
    if (n >= N) return;

    const float4* xp = (const float4*)(x + (size_t)n * 16);
    float4 v0 = xp[0], v1 = xp[1], v2 = xp[2], v3 = xp[3];
    float xr[16] = { v0.x, v0.y, v0.z, v0.w,  v1.x, v1.y, v1.z, v1.w,
                     v2.x, v2.y, v2.z, v2.w,  v3.x, v3.y, v3.z, v3.w };

    float dinv = rsqrtf((float)(g_deg[n] + 1));   // +1 self loop; always > 0
    g_dinv[n] = dinv;

    float h[8];
#pragma unroll
    for (int j = 0; j < 8; j++) {
        float s = 0.f;
#pragma unroll
        for (int i = 0; i < 16; i++) s = fmaf(xr[i], sW[j * 16 + i], s);
        h[j] = s * dinv;
    }

    float4 a = make_float4(h[0], h[1], h[2], h[3]);
    float4 c = make_float4(h[4], h[5], h[6], h[7]);

    float4* hsp = (float4*)(g_hs + (size_t)n * 8);
    hsp[0] = a; hsp[1] = c;
    float4* op = (float4*)(out + (size_t)n * 8);
    op[0] = a; op[1] = c;                   // accumulator init = self-loop msg
}

// ---------------------------------------------------------------- edge scatter
// out[dst] += hs[src], 1 edge/thread (max warp-level RED concurrency).
__global__ void k_scatter(const int* __restrict__ src,
                          const int* __restrict__ dst,
                          float* __restrict__ out, int E, int N) {
    int e = blockIdx.x * blockDim.x + threadIdx.x;
    if (e >= E) return;

    int s = src[e];
    int d = dst[e];
    if ((unsigned)s >= (unsigned)N || (unsigned)d >= (unsigned)N) return;

    const float4* hp = (const float4*)(g_hs + (size_t)s * 8);
    float4 a = hp[0], c = hp[1];

    float* dp = out + (size_t)d * 8;
    asm volatile("red.global.add.v4.f32 [%0], {%1,%2,%3,%4};"
                 :: "l"(dp), "f"(a.x), "f"(a.y), "f"(a.z), "f"(a.w) : "memory");
    asm volatile("red.global.add.v4.f32 [%0], {%1,%2,%3,%4};"
                 :: "l"(dp + 4), "f"(c.x), "f"(c.y), "f"(c.z), "f"(c.w) : "memory");
}

// ---------------------------------------------------------------- finalize: out = out*dinv + b
__global__ void k_final(const float* __restrict__ bias, float* __restrict__ out, int N) {
    int n = blockIdx.x * blockDim.x + threadIdx.x;
    if (n >= N) return;

    float dinv = g_dinv[n];
    const float4* bp = (const float4*)bias;
    float4 b0 = __ldg(bp), b1 = __ldg(bp + 1);

    float4* op = (float4*)(out + (size_t)n * 8);
    float4 a = op[0], c = op[1];
    a.x = fmaf(a.x, dinv, b0.x); a.y = fmaf(a.y, dinv, b0.y);
    a.z = fmaf(a.z, dinv, b0.z); a.w = fmaf(a.w, dinv, b0.w);
    c.x = fmaf(c.x, dinv, b1.x); c.y = fmaf(c.y, dinv, b1.y);
    c.z = fmaf(c.z, dinv, b1.z); c.w = fmaf(c.w, dinv, b1.w);
    op[0] = a; op[1] = c;
}

// ---------------------------------------------------------------- launch
extern "C" void kernel_launch(void* const* d_in, const int* in_sizes, int n_in,
                              void* d_out, int out_size) {
    const float* x    = (const float*)d_in[0];   // [N,16] f32
    const int*   ei   = (const int*)d_in[1];     // [2,E]  int32 (converted from int64)
    const float* W    = (const float*)d_in[2];   // [8,16] f32
    const float* bias = (const float*)d_in[3];   // [8]    f32
    float*       out  = (float*)d_out;           // [N,8]  f32

    int N = in_sizes[0] / 16;
    int E = in_sizes[1] / 2;
    const int* src = ei;
    const int* dst = ei + E;

    const int T = 256;
    int gbN  = (N + T - 1) / T;
    int gbE4 = (E / 4 + T - 1) / T + 1;      // 4 edges/thread (+1 tail block)
    int gbE1 = (E + T - 1) / T;              // 1 edge/thread

    void* degp = nullptr;
    cudaGetSymbolAddress(&degp, g_deg);      // address query only, no allocation
    cudaMemsetAsync(degp, 0, (size_t)N * sizeof(int));

    k_deg<<<gbE4, T>>>(dst, E, N);
    k_node<<<gbN, T>>>(x, W, out, N);
    k_scatter<<<gbE1, T>>>(src, dst, out, E, N);
    k_final<<<gbN, T>>>(bias, out, N);
}

// round 15
// speedup vs baseline: 1.5539x; 1.0516x over previous
#include <cuda_runtime.h>
#include <cstddef>

// GCNConv(16,8): out = D^-1/2 (A+I) D^-1/2 X W^T + b
// Final configuration: scatter-RED at the measured LTS atomic-op floor.
//   hs[n]   = dinv[n] * (x[n] @ W^T),  dinv[n] = rsqrt(deg[n]+1)
//   out[n]  = hs[n]                       (init + L2 pre-warm, k_node)
//   out[d] += hs[s]      per edge         (k_scatter, 2 edges/thread, 2x red.v4)
//   out[n]  = out[n]*dinv[n] + b          (k_final)

#define MAXN 500000

__device__ float g_hs[(size_t)MAXN * 8];    // 16 MB, L2-resident
__device__ float g_dinv[MAXN];
__device__ int   g_deg[MAXN];

// ---------------------------------------------------------------- degree count (2 edges/thread)
__global__ void k_deg(const int* __restrict__ dst, int E, int N) {
    int i = blockIdx.x * blockDim.x + threadIdx.x;
    int e = i * 2;
    if (e >= E) return;

    int2 d2;
    if (e + 1 < E) {
        d2 = *(const int2*)(dst + e);
    } else {
        d2.x = dst[e];
        d2.y = -1;                          // fails bounds check
    }
    if ((unsigned)d2.x < (unsigned)N) atomicAdd(&g_deg[d2.x], 1);
    if ((unsigned)d2.y < (unsigned)N) atomicAdd(&g_deg[d2.y], 1);
}

// ---------------------------------------------------------------- node transform
// hs = dinv * (x @ W^T); out initialized to hs (self-loop msg + L2 pre-warm).
__global__ void k_node(const float* __restrict__ x, const float* __restrict__ W,
                       float* __restrict__ out, int N) {
    __shared__ float sW[128];               // W is [8,16] row-major
    int t = threadIdx.x;
    if (t < 128) sW[t] = W[t];
    __syncthreads();

    int n = blockIdx.x * blockDim.x + t;
    if (n >= N) return;

    const float4* xp = (const float4*)(x + (size_t)n * 16);
    float4 v0 = xp[0], v1 = xp[1], v2 = xp[2], v3 = xp[3];
    float xr[16] = { v0.x, v0.y, v0.z, v0.w,  v1.x, v1.y, v1.z, v1.w,
                     v2.x, v2.y, v2.z, v2.w,  v3.x, v3.y, v3.z, v3.w };

    float dinv = rsqrtf((float)(g_deg[n] + 1));   // +1 self loop; always > 0
    g_dinv[n] = dinv;

    float h[8];
#pragma unroll
    for (int j = 0; j < 8; j++) {
        float s = 0.f;
#pragma unroll
        for (int i = 0; i < 16; i++) s = fmaf(xr[i], sW[j * 16 + i], s);
        h[j] = s * dinv;
    }

    float4 a = make_float4(h[0], h[1], h[2], h[3]);
    float4 c = make_float4(h[4], h[5], h[6], h[7]);

    float4* hsp = (float4*)(g_hs + (size_t)n * 8);
    hsp[0] = a; hsp[1] = c;
    float4* op = (float4*)(out + (size_t)n * 8);
    op[0] = a; op[1] = c;                   // accumulator init = self-loop msg
}

// ---------------------------------------------------------------- edge scatter
// out[dst] += hs[src], 2 edges/thread (measured optimum), 2x red.v4.f32/edge.
__global__ void k_scatter(const int* __restrict__ src,
                          const int* __restrict__ dst,
                          float* __restrict__ out, int E, int N) {
    int i = blockIdx.x * blockDim.x + threadIdx.x;
    int e = i * 2;
    if (e >= E) return;

    int2 s2, d2;
    if (e + 1 < E) {
        s2 = *(const int2*)(src + e);
        d2 = *(const int2*)(dst + e);
    } else {
        s2.x = src[e]; d2.x = dst[e];
        s2.y = 0;      d2.y = -1;           // fails bounds check
    }

#pragma unroll
    for (int j = 0; j < 2; j++) {
        int s = j ? s2.y : s2.x;
        int d = j ? d2.y : d2.x;
        if ((unsigned)s >= (unsigned)N || (unsigned)d >= (unsigned)N) continue;

        const float4* hp = (const float4*)(g_hs + (size_t)s * 8);
        float4 a = hp[0], c = hp[1];

        float* dp = out + (size_t)d * 8;
        asm volatile("red.global.add.v4.f32 [%0], {%1,%2,%3,%4};"
                     :: "l"(dp), "f"(a.x), "f"(a.y), "f"(a.z), "f"(a.w) : "memory");
        asm volatile("red.global.add.v4.f32 [%0], {%1,%2,%3,%4};"
                     :: "l"(dp + 4), "f"(c.x), "f"(c.y), "f"(c.z), "f"(c.w) : "memory");
    }
}

// ---------------------------------------------------------------- finalize: out = out*dinv + b
__global__ void k_final(const float* __restrict__ bias, float* __restrict__ out, int N) {
    int n = blockIdx.x * blockDim.x + threadIdx.x;
    if (n >= N) return;

    float dinv = g_dinv[n];
    const float4* bp = (const float4*)bias;
    float4 b0 = __ldg(bp), b1 = __ldg(bp + 1);

    float4* op = (float4*)(out + (size_t)n * 8);
    float4 a = op[0], c = op[1];
    a.x = fmaf(a.x, dinv, b0.x); a.y = fmaf(a.y, dinv, b0.y);
    a.z = fmaf(a.z, dinv, b0.z); a.w = fmaf(a.w, dinv, b0.w);
    c.x = fmaf(c.x, dinv, b1.x); c.y = fmaf(c.y, dinv, b1.y);
    c.z = fmaf(c.z, dinv, b1.z); c.w = fmaf(c.w, dinv, b1.w);
    op[0] = a; op[1] = c;
}

// ---------------------------------------------------------------- launch
extern "C" void kernel_launch(void* const* d_in, const int* in_sizes, int n_in,
                              void* d_out, int out_size) {
    const float* x    = (const float*)d_in[0];   // [N,16] f32
    const int*   ei   = (const int*)d_in[1];     // [2,E]  int32 (converted from int64)
    const float* W    = (const float*)d_in[2];   // [8,16] f32
    const float* bias = (const float*)d_in[3];   // [8]    f32
    float*       out  = (float*)d_out;           // [N,8]  f32

    int N = in_sizes[0] / 16;
    int E = in_sizes[1] / 2;
    const int* src = ei;
    const int* dst = ei + E;

    const int T = 256;
    int gbN  = (N + T - 1) / T;
    int gbE2 = ((E + 1) / 2 + T - 1) / T;    // 2 edges/thread

    void* degp = nullptr;
    cudaGetSymbolAddress(&degp, g_deg);      // address query only, no allocation
    cudaMemsetAsync(degp, 0, (size_t)N * sizeof(int));

    k_deg<<<gbE2, T>>>(dst, E, N);
    k_node<<<gbN, T>>>(x, W, out, N);
    k_scatter<<<gbE2, T>>>(src, dst, out, E, N);
    k_final<<<gbN, T>>>(bias, out, N);
}

// round 16
// speedup vs baseline: 1.5579x; 1.0025x over previous
#include <cuda_runtime.h>
#include <cstddef>

// GCNConv(16,8): out = D^-1/2 (A+I) D^-1/2 X W^T + b
// Scatter-RED at the measured LTS atomic-op floor. R15 config with T=512
// on the two LTS-bound edge kernels (block-geometry probe).
//   hs[n]   = dinv[n] * (x[n] @ W^T),  dinv[n] = rsqrt(deg[n]+1)
//   out[n]  = hs[n]                       (init + L2 pre-warm, k_node)
//   out[d] += hs[s]      per edge         (k_scatter, 2 edges/thread, 2x red.v4)
//   out[n]  = out[n]*dinv[n] + b          (k_final)

#define MAXN 500000

__device__ float g_hs[(size_t)MAXN * 8];    // 16 MB, L2-resident
__device__ float g_dinv[MAXN];
__device__ int   g_deg[MAXN];

// ---------------------------------------------------------------- degree count (2 edges/thread)
__global__ void k_deg(const int* __restrict__ dst, int E, int N) {
    int i = blockIdx.x * blockDim.x + threadIdx.x;
    int e = i * 2;
    if (e >= E) return;

    int2 d2;
    if (e + 1 < E) {
        d2 = *(const int2*)(dst + e);
    } else {
        d2.x = dst[e];
        d2.y = -1;                          // fails bounds check
    }
    if ((unsigned)d2.x < (unsigned)N) atomicAdd(&g_deg[d2.x], 1);
    if ((unsigned)d2.y < (unsigned)N) atomicAdd(&g_deg[d2.y], 1);
}

// ---------------------------------------------------------------- node transform
// hs = dinv * (x @ W^T); out initialized to hs (self-loop msg + L2 pre-warm).
__global__ void k_node(const float* __restrict__ x, const float* __restrict__ W,
                       float* __restrict__ out, int N) {
    __shared__ float sW[128];               // W is [8,16] row-major
    int t = threadIdx.x;
    if (t < 128) sW[t] = W[t];
    __syncthreads();

    int n = blockIdx.x * blockDim.x + t;
    if (n >= N) return;

    const float4* xp = (const float4*)(x + (size_t)n * 16);
    float4 v0 = xp[0], v1 = xp[1], v2 = xp[2], v3 = xp[3];
    float xr[16] = { v0.x, v0.y, v0.z, v0.w,  v1.x, v1.y, v1.z, v1.w,
                     v2.x, v2.y, v2.z, v2.w,  v3.x, v3.y, v3.z, v3.w };

    float dinv = rsqrtf((float)(g_deg[n] + 1));   // +1 self loop; always > 0
    g_dinv[n] = dinv;

    float h[8];
#pragma unroll
    for (int j = 0; j < 8; j++) {
        float s = 0.f;
#pragma unroll
        for (int i = 0; i < 16; i++) s = fmaf(xr[i], sW[j * 16 + i], s);
        h[j] = s * dinv;
    }

    float4 a = make_float4(h[0], h[1], h[2], h[3]);
    float4 c = make_float4(h[4], h[5], h[6], h[7]);

    float4* hsp = (float4*)(g_hs + (size_t)n * 8);
    hsp[0] = a; hsp[1] = c;
    float4* op = (float4*)(out + (size_t)n * 8);
    op[0] = a; op[1] = c;                   // accumulator init = self-loop msg
}

// ---------------------------------------------------------------- edge scatter
// out[dst] += hs[src], 2 edges/thread (measured optimum), 2x red.v4.f32/edge.
__global__ void k_scatter(const int* __restrict__ src,
                          const int* __restrict__ dst,
                          float* __restrict__ out, int E, int N) {
    int i = blockIdx.x * blockDim.x + threadIdx.x;
    int e = i * 2;
    if (e >= E) return;

    int2 s2, d2;
    if (e + 1 < E) {
        s2 = *(const int2*)(src + e);
        d2 = *(const int2*)(dst + e);
    } else {
        s2.x = src[e]; d2.x = dst[e];
        s2.y = 0;      d2.y = -1;           // fails bounds check
    }

#pragma unroll
    for (int j = 0; j < 2; j++) {
        int s = j ? s2.y : s2.x;
        int d = j ? d2.y : d2.x;
        if ((unsigned)s >= (unsigned)N || (unsigned)d >= (unsigned)N) continue;

        const float4* hp = (const float4*)(g_hs + (size_t)s * 8);
        float4 a = hp[0], c = hp[1];

        float* dp = out + (size_t)d * 8;
        asm volatile("red.global.add.v4.f32 [%0], {%1,%2,%3,%4};"
                     :: "l"(dp), "f"(a.x), "f"(a.y), "f"(a.z), "f"(a.w) : "memory");
        asm volatile("red.global.add.v4.f32 [%0], {%1,%2,%3,%4};"
                     :: "l"(dp + 4), "f"(c.x), "f"(c.y), "f"(c.z), "f"(c.w) : "memory");
    }
}

// ---------------------------------------------------------------- finalize: out = out*dinv + b
__global__ void k_final(const float* __restrict__ bias, float* __restrict__ out, int N) {
    int n = blockIdx.x * blockDim.x + threadIdx.x;
    if (n >= N) return;

    float dinv = g_dinv[n];
    const float4* bp = (const float4*)bias;
    float4 b0 = __ldg(bp), b1 = __ldg(bp + 1);

    float4* op = (float4*)(out + (size_t)n * 8);
    float4 a = op[0], c = op[1];
    a.x = fmaf(a.x, dinv, b0.x); a.y = fmaf(a.y, dinv, b0.y);
    a.z = fmaf(a.z, dinv, b0.z); a.w = fmaf(a.w, dinv, b0.w);
    c.x = fmaf(c.x, dinv, b1.x); c.y = fmaf(c.y, dinv, b1.y);
    c.z = fmaf(c.z, dinv, b1.z); c.w = fmaf(c.w, dinv, b1.w);
    op[0] = a; op[1] = c;
}

// ---------------------------------------------------------------- launch
extern "C" void kernel_launch(void* const* d_in, const int* in_sizes, int n_in,
                              void* d_out, int out_size) {
    const float* x    = (const float*)d_in[0];   // [N,16] f32
    const int*   ei   = (const int*)d_in[1];     // [2,E]  int32 (converted from int64)
    const float* W    = (const float*)d_in[2];   // [8,16] f32
    const float* bias = (const float*)d_in[3];   // [8]    f32
    float*       out  = (float*)d_out;           // [N,8]  f32

    int N = in_sizes[0] / 16;
    int E = in_sizes[1] / 2;
    const int* src = ei;
    const int* dst = ei + E;

    const int TN = 256;                      // node/final kernels
    const int TE = 512;                      // LTS-bound edge kernels
    int gbN  = (N + TN - 1) / TN;
    int gbE2 = ((E + 1) / 2 + TE - 1) / TE;  // 2 edges/thread

    void* degp = nullptr;
    cudaGetSymbolAddress(&degp, g_deg);      // address query only, no allocation
    cudaMemsetAsync(degp, 0, (size_t)N * sizeof(int));

    k_deg<<<gbE2, TE>>>(dst, E, N);
    k_node<<<gbN, TN>>>(x, W, out, N);
    k_scatter<<<gbE2, TE>>>(src, dst, out, E, N);
    k_final<<<gbN, TN>>>(bias, out, N);
}